// round 15
// baseline (speedup 1.0000x reference)
// v14: 256-step scan tiles + hoisted ratio constants; GEMM unchanged
#include <cuda_runtime.h>
#include <cuda_fp16.h>
#include <cstdint>
#include <cstddef>

#define Bdim 8
#define Ndim 4096
#define Cdim 512
#define Hdim 4
#define Mdim (Bdim*Ndim)   /* 32768 */
#define Kdim (2*Cdim)      /* 1024  */

// A (scan output) [M][K] fp16; B (proj_w) [N][K] fp16
__device__ __align__(128) __half g_a[(size_t)Mdim * Kdim];
__device__ __align__(128) __half g_b[(size_t)Cdim * Kdim];

__device__ __forceinline__ float ex2f(float x) {
    float y;
    asm("ex2.approx.ftz.f32 %0, %1;" : "=f"(y) : "f"(x));
    return y;
}

__device__ __forceinline__ uint32_t smem_u32(const void* p) {
    uint32_t a;
    asm("{ .reg .u64 t; cvta.to.shared.u64 t, %1; cvt.u32.u64 %0, t; }" : "=r"(a) : "l"(p));
    return a;
}

__device__ __forceinline__ void cp16(uint32_t dst, const void* src) {
    asm volatile("cp.async.cg.shared.global [%0], [%1], 16;" :: "r"(dst), "l"(src));
}

__device__ __forceinline__ void ldsm4(uint32_t* r, uint32_t a) {
    asm volatile("ldmatrix.sync.aligned.m8n8.x4.shared.b16 {%0,%1,%2,%3}, [%4];"
        : "=r"(r[0]), "=r"(r[1]), "=r"(r[2]), "=r"(r[3]) : "r"(a));
}

__device__ __forceinline__ void mma16816(float* d, const uint32_t* a, const uint32_t* b) {
    asm volatile("mma.sync.aligned.m16n8k16.row.col.f32.f16.f16.f32 "
        "{%0,%1,%2,%3}, {%4,%5,%6,%7}, {%8,%9}, {%0,%1,%2,%3};"
        : "+f"(d[0]), "+f"(d[1]), "+f"(d[2]), "+f"(d[3])
        : "r"(a[0]), "r"(a[1]), "r"(a[2]), "r"(a[3]), "r"(b[0]), "r"(b[1]));
}

// ---------------------------------------------------------------------------
// W convert
// ---------------------------------------------------------------------------
__global__ void wconv_kernel(const float* __restrict__ W)
{
    int i = blockIdx.x * 256 + threadIdx.x;   // 2048 x 256
    g_b[i] = __float2half_rn(W[i]);
}

// ---------------------------------------------------------------------------
// Clipped EMA scan (fwd + bwd) -> fp16 in [M][K]
// grid = 2*B*(C/8) = 1024 blocks, 256 threads (8 warps = 8 channels)
// 256-step tiles: 8 elems/thread serial + one warp scan; 2 syncs/tile
// ---------------------------------------------------------------------------
#define XSTR 260
#define YSTR 260

__global__ __launch_bounds__(256) void scan_kernel(
    const float* __restrict__ x,
    const float* __restrict__ al, const float* __restrict__ dl,
    const float* __restrict__ bl, const float* __restrict__ eta)
{
    const int CG = Cdim / 8;
    int blk = blockIdx.x;
    int cg  = blk % CG;
    int b   = (blk / CG) % Bdim;
    int dir = blk / (CG * Bdim);
    int c0  = cg * 8;

    __shared__ float xs[8 * XSTR];        // [c][t]
    __shared__ float ys[2][8 * YSTR];     // double-buffered [c][t]
    __shared__ float sA[8][4], sLr[8][4], sEt[8][4];

    int tid = threadIdx.x;
    if (tid < 32) {
        int cc = tid >> 2, hh = tid & 3;
        int idx = (c0 + cc) * Hdim + hh;
        float a  = 1.0f / (1.0f + expf(-al[idx]));
        float dd = 1.0f / (1.0f + expf(-dl[idx]));
        float be = 1.0f / (1.0f + expf(-bl[idx]));
        float r  = 1.0f - a * dd;
        r = fminf(fmaxf(r, 1e-4f), 1.0f - 1e-4f);
        sA[cc][hh]  = a * be;
        sLr[cc][hh] = log2f(r);
        sEt[cc][hh] = eta[idx];
    }
    __syncthreads();

    int w = tid >> 5, lane = tid & 31;
    const float QC = 1.1420074e+26f;   // exp(60)
    const float PC = 8.7565108e-27f;   // exp(-60)
    float Ah[4], Lr[4], Et[4], carry[4], AhQ[4], EtP[4], Rp[4], Rq[4];
#pragma unroll
    for (int hh = 0; hh < 4; hh++) {
        Ah[hh] = sA[w][hh]; Lr[hh] = sLr[w][hh]; Et[hh] = sEt[w][hh];
        carry[hh] = 0.0f;
        AhQ[hh] = Ah[hh] * QC;
        EtP[hh] = Et[hh] * PC;
        Rp[hh]  = ex2f(Lr[hh]);    // r
        Rq[hh]  = ex2f(-Lr[hh]);   // 1/r
    }

    const float CLP = 86.56170245333781f;   // 60 * log2(e)

    for (int tt = 0; tt < Ndim / 256; tt++) {
        int t0 = tt * 256;
        // load: thread tid handles row t0+tid, transposed store of 8 channels
        {
            int n_ld = dir ? (Ndim - 1 - (t0 + tid)) : (t0 + tid);
            const float* xr = &x[((size_t)b * Ndim + n_ld) * Cdim + c0];
            float4 v0 = *(const float4*)xr;
            float4 v1 = *(const float4*)(xr + 4);
            xs[0 * XSTR + tid] = v0.x; xs[1 * XSTR + tid] = v0.y;
            xs[2 * XSTR + tid] = v0.z; xs[3 * XSTR + tid] = v0.w;
            xs[4 * XSTR + tid] = v1.x; xs[5 * XSTR + tid] = v1.y;
            xs[6 * XSTR + tid] = v1.z; xs[7 * XSTR + tid] = v1.w;
        }
        __syncthreads();

        float xv[8], yv[8];
        *(float4*)(xv)     = *(const float4*)&xs[w * XSTR + lane * 8];
        *(float4*)(xv + 4) = *(const float4*)&xs[w * XSTR + lane * 8 + 4];
#pragma unroll
        for (int j = 0; j < 8; j++) yv[j] = 0.0f;
        float s0f = (float)(t0 + lane * 8);
        float tf0 = (float)t0;

#pragma unroll
        for (int hh = 0; hh < 4; hh++) {
            float lr = Lr[hh];
            float z[8], mu[8];
            if (lr * tf0 <= -CLP) {
                // fully clamped: constants, zero MUFU
                float aq = AhQ[hh], ep = EtP[hh];
#pragma unroll
                for (int j = 0; j < 8; j++) { z[j] = aq * xv[j]; mu[j] = ep; }
            } else if (lr * (tf0 + 255.0f) >= -CLP) {
                // fully unclamped: 2 MUFU, ratio chains
                float e0 = lr * s0f;
                float zq = Ah[hh] * ex2f(-e0);
                float mp = Et[hh] * ex2f(e0);
                float rq = Rq[hh], rp = Rp[hh];
#pragma unroll
                for (int j = 0; j < 8; j++) {
                    z[j] = zq * xv[j]; mu[j] = mp;
                    zq *= rq; mp *= rp;
                }
            } else {
                // crossing tile (<=1 per channel): exact per element
#pragma unroll
                for (int j = 0; j < 8; j++) {
                    float e = fmaxf(lr * (s0f + (float)j), -CLP);
                    mu[j] = Et[hh] * ex2f(e);
                    z[j]  = Ah[hh] * xv[j] * ex2f(-e);
                }
            }
#pragma unroll
            for (int j = 1; j < 8; j++) z[j] += z[j - 1];
            float tot = z[7];
            float ss = tot;
#pragma unroll
            for (int o = 1; o < 32; o <<= 1) {
                float v = __shfl_up_sync(0xffffffffu, ss, o);
                if (lane >= o) ss += v;
            }
            float blkTot = __shfl_sync(0xffffffffu, ss, 31);
            float pre = ss - tot + carry[hh];
#pragma unroll
            for (int j = 0; j < 8; j++)
                yv[j] = fmaf(mu[j], pre + z[j], yv[j]);
            carry[hh] += blkTot;
        }

        int pb = tt & 1;
        *(float4*)&ys[pb][w * YSTR + lane * 8]     = *(float4*)(yv);
        *(float4*)&ys[pb][w * YSTR + lane * 8 + 4] = *(float4*)(yv + 4);
        __syncthreads();

        // writers: thread tid packs 8 channels of timestep t0+tid (fp16)
        {
            int n_st = dir ? (Ndim - 1 - (t0 + tid)) : (t0 + tid);
            size_t m = (size_t)b * Ndim + n_st;
            uint4 u;
            unsigned* up = (unsigned*)&u;
#pragma unroll
            for (int j = 0; j < 4; j++) {
                __half2 pk = __floats2half2_rn(ys[pb][(2 * j) * YSTR + tid],
                                               ys[pb][(2 * j + 1) * YSTR + tid]);
                up[j] = *(unsigned*)&pk;
            }
            *(uint4*)(g_a + m * Kdim + dir * Cdim + c0) = u;
        }
        // no sync needed: next tile writes xs (disjoint) and ys[pb^1]
    }
}

// ---------------------------------------------------------------------------
// fp16 HMMA GEMM: out[m][n] = bias[n] + sum_k z[m][k]W[n][k]
// CTA tile 128x128, K-chunk 64, 3-stage cp.async, 256 threads, 2 CTAs/SM.
// ---------------------------------------------------------------------------
#define ROWB2 144                            /* 128 data + 16 pad */
#define A_OFF 0
#define B_OFF (128*ROWB2)                    /* 18432 */
#define STG2 (2*128*ROWB2)                   /* 36864 */
#define BIAS2 (3*STG2)                       /* 110592 */
#define GSM (BIAS2 + 512)

__global__ void __launch_bounds__(256, 2) gemm_hmma(const float* __restrict__ bias,
                                                    float* __restrict__ out)
{
    extern __shared__ char smem[];
    const uint32_t sb = smem_u32(smem);
    int tid  = threadIdx.x;
    int wid  = tid >> 5, lane = tid & 31;
    int n0   = blockIdx.x * 128;
    int m0   = blockIdx.y * 128;
    int wm   = (wid & 1) * 64;
    int wn   = (wid >> 1) * 32;

    if (tid < 128) ((float*)(smem + BIAS2))[tid] = bias[n0 + tid];

    auto load_chunk = [&](int kt, int buf) {
        uint32_t st = sb + (uint32_t)buf * STG2;
        int koff = kt * 64;
#pragma unroll
        for (int i = 0; i < 4; i++) {
            int q = tid + i * 256;           // 0..1023
            int r = q >> 3, c = q & 7;
            cp16(st + A_OFF + r * ROWB2 + c * 16,
                 g_a + (size_t)(m0 + r) * Kdim + koff + c * 8);
            cp16(st + B_OFF + r * ROWB2 + c * 16,
                 g_b + (size_t)(n0 + r) * Kdim + koff + c * 8);
        }
        asm volatile("cp.async.commit_group;" ::: "memory");
    };

    const uint32_t a_off =
        (uint32_t)((wm + (lane & 7) + ((lane >> 3) & 1) * 8) * ROWB2 + ((lane >> 4) & 1) * 16);
    const uint32_t b_off =
        (uint32_t)((wn + (lane & 7) + ((lane >> 4) & 1) * 8) * ROWB2 + ((lane >> 3) & 1) * 16);

    float acc[4][4][4];
#pragma unroll
    for (int mi = 0; mi < 4; mi++)
#pragma unroll
        for (int ni = 0; ni < 4; ni++)
#pragma unroll
            for (int j = 0; j < 4; j++) acc[mi][ni][j] = 0.0f;

    load_chunk(0, 0);
    load_chunk(1, 1);

    for (int kt = 0; kt < 16; kt++) {
        if (kt + 2 < 16) load_chunk(kt + 2, (kt + 2) % 3);
        if (kt < 14)       asm volatile("cp.async.wait_group 2;" ::: "memory");
        else if (kt == 14) asm volatile("cp.async.wait_group 1;" ::: "memory");
        else               asm volatile("cp.async.wait_group 0;" ::: "memory");
        __syncthreads();

        uint32_t st = sb + (uint32_t)(kt % 3) * STG2;
#pragma unroll
        for (int s = 0; s < 4; s++) {
            uint32_t af[4][4], bf2[4][2];
#pragma unroll
            for (int mi = 0; mi < 4; mi++)
                ldsm4(af[mi], st + A_OFF + a_off + mi * 16 * ROWB2 + s * 32);
#pragma unroll
            for (int j = 0; j < 2; j++) {
                uint32_t t4[4];
                ldsm4(t4, st + B_OFF + b_off + j * 16 * ROWB2 + s * 32);
                bf2[2 * j][0] = t4[0]; bf2[2 * j][1] = t4[1];
                bf2[2 * j + 1][0] = t4[2]; bf2[2 * j + 1][1] = t4[3];
            }
#pragma unroll
            for (int mi = 0; mi < 4; mi++)
#pragma unroll
                for (int ni = 0; ni < 4; ni++)
                    mma16816(acc[mi][ni], af[mi], bf2[ni]);
        }
        __syncthreads();
    }

    asm volatile("cp.async.wait_all;" ::: "memory");
    __syncthreads();

    // epilogue: regs -> padded smem -> +bias -> coalesced float4 STG
    float* stg = (float*)smem;               // [128][132]
#pragma unroll
    for (int mi = 0; mi < 4; mi++)
#pragma unroll
        for (int ni = 0; ni < 4; ni++) {
            int r0 = wm + mi * 16 + (lane >> 2);
            int cc = wn + ni * 8 + (lane & 3) * 2;
            *(float2*)&stg[r0 * 132 + cc]       = make_float2(acc[mi][ni][0], acc[mi][ni][1]);
            *(float2*)&stg[(r0 + 8) * 132 + cc] = make_float2(acc[mi][ni][2], acc[mi][ni][3]);
        }
    __syncthreads();
    const float* bsm = (const float*)(smem + BIAS2);
#pragma unroll
    for (int i = 0; i < 16; i++) {
        int f = tid + i * 256;
        int r = f >> 5, c4 = (f & 31) * 4;
        float4 v = *(const float4*)&stg[r * 132 + c4];
        v.x += bsm[c4]; v.y += bsm[c4 + 1]; v.z += bsm[c4 + 2]; v.w += bsm[c4 + 3];
        *(float4*)&out[(size_t)(m0 + r) * Cdim + n0 + c4] = v;
    }
}

// ---------------------------------------------------------------------------
extern "C" void kernel_launch(void* const* d_in, const int* in_sizes, int n_in,
                              void* d_out, int out_size)
{
    const float* x  = (const float*)d_in[0];
    const float* al = (const float*)d_in[1];
    const float* dl = (const float*)d_in[2];
    const float* bl = (const float*)d_in[3];
    const float* et = (const float*)d_in[4];
    const float* pw = (const float*)d_in[5];
    const float* pb = (const float*)d_in[6];
    float* out = (float*)d_out;

    cudaFuncSetAttribute(gemm_hmma, cudaFuncAttributeMaxDynamicSharedMemorySize, GSM);

    wconv_kernel<<<2048, 256>>>(pw);
    scan_kernel<<<dim3(2 * Bdim * (Cdim / 8)), 256>>>(x, al, dl, bl, et);
    gemm_hmma<<<dim3(Cdim / 128, Mdim / 128), 256, GSM>>>(pb, out);
}

// round 16
// speedup vs baseline: 1.6744x; 1.6744x over previous
// v16: v12 base (231.5us) + collapsed all-clamped scan path; GEMM/wconv unchanged
#include <cuda_runtime.h>
#include <cuda_fp16.h>
#include <cstdint>
#include <cstddef>

#define Bdim 8
#define Ndim 4096
#define Cdim 512
#define Hdim 4
#define Mdim (Bdim*Ndim)   /* 32768 */
#define Kdim (2*Cdim)      /* 1024  */

// A (scan output) [M][K] fp16; B (proj_w) [N][K] fp16
__device__ __align__(128) __half g_a[(size_t)Mdim * Kdim];
__device__ __align__(128) __half g_b[(size_t)Cdim * Kdim];

__device__ __forceinline__ float ex2f(float x) {
    float y;
    asm("ex2.approx.ftz.f32 %0, %1;" : "=f"(y) : "f"(x));
    return y;
}

__device__ __forceinline__ uint32_t smem_u32(const void* p) {
    uint32_t a;
    asm("{ .reg .u64 t; cvta.to.shared.u64 t, %1; cvt.u32.u64 %0, t; }" : "=r"(a) : "l"(p));
    return a;
}

__device__ __forceinline__ void cp16(uint32_t dst, const void* src) {
    asm volatile("cp.async.cg.shared.global [%0], [%1], 16;" :: "r"(dst), "l"(src));
}

__device__ __forceinline__ void ldsm4(uint32_t* r, uint32_t a) {
    asm volatile("ldmatrix.sync.aligned.m8n8.x4.shared.b16 {%0,%1,%2,%3}, [%4];"
        : "=r"(r[0]), "=r"(r[1]), "=r"(r[2]), "=r"(r[3]) : "r"(a));
}

__device__ __forceinline__ void mma16816(float* d, const uint32_t* a, const uint32_t* b) {
    asm volatile("mma.sync.aligned.m16n8k16.row.col.f32.f16.f16.f32 "
        "{%0,%1,%2,%3}, {%4,%5,%6,%7}, {%8,%9}, {%0,%1,%2,%3};"
        : "+f"(d[0]), "+f"(d[1]), "+f"(d[2]), "+f"(d[3])
        : "r"(a[0]), "r"(a[1]), "r"(a[2]), "r"(a[3]), "r"(b[0]), "r"(b[1]));
}

// ---------------------------------------------------------------------------
// W convert: g_b[n][k] = fp16(proj_w[n][k])
// ---------------------------------------------------------------------------
__global__ void wconv_kernel(const float* __restrict__ W)
{
    int i = blockIdx.x * 256 + threadIdx.x;   // 2048 x 256
    g_b[i] = __float2half_rn(W[i]);
}

// ---------------------------------------------------------------------------
// Clipped EMA scan (fwd + bwd) -> fp16 in [M][K]
// grid = 2*B*(C/8) = 1024 blocks, 256 threads (8 warps = 8 channels)
// 128-step tiles (v12 structure). NEW: when ALL 4 h of a channel are in the
// clamped regime, the 4 per-h scans collapse into ONE scan of raw x.
// ---------------------------------------------------------------------------
#define XS_STRIDE 140
#define YS_STRIDE 136

__global__ __launch_bounds__(256) void scan_kernel(
    const float* __restrict__ x,
    const float* __restrict__ al, const float* __restrict__ dl,
    const float* __restrict__ bl, const float* __restrict__ eta)
{
    const int CG = Cdim / 8;
    int blk = blockIdx.x;
    int cg  = blk % CG;
    int b   = (blk / CG) % Bdim;
    int dir = blk / (CG * Bdim);
    int c0  = cg * 8;

    __shared__ float xs2[8 * XS_STRIDE];   // [c][t]
    __shared__ float ys2[8 * YS_STRIDE];   // [c][t]
    __shared__ float sA[8][4], sLr[8][4], sEt[8][4];

    int tid = threadIdx.x;
    if (tid < 32) {
        int cc = tid >> 2, hh = tid & 3;
        int idx = (c0 + cc) * Hdim + hh;
        float a  = 1.0f / (1.0f + expf(-al[idx]));
        float dd = 1.0f / (1.0f + expf(-dl[idx]));
        float be = 1.0f / (1.0f + expf(-bl[idx]));
        float r  = 1.0f - a * dd;
        r = fminf(fmaxf(r, 1e-4f), 1.0f - 1e-4f);
        sA[cc][hh]  = a * be;
        sLr[cc][hh] = log2f(r);
        sEt[cc][hh] = eta[idx];
    }
    __syncthreads();

    int w = tid >> 5, lane = tid & 31;
    const float QC = 1.1420074e+26f;   // exp(60)
    const float PC = 8.7565108e-27f;   // exp(-60)
    float Ah[4], Lr[4], Et[4], carry[4], AhQ[4], EtP[4];
#pragma unroll
    for (int hh = 0; hh < 4; hh++) {
        Ah[hh] = sA[w][hh]; Lr[hh] = sLr[w][hh]; Et[hh] = sEt[w][hh];
        carry[hh] = 0.0f;
        AhQ[hh] = Ah[hh] * QC;
        EtP[hh] = Et[hh] * PC;
    }
    // collapsed-path constants
    float lrmax = fmaxf(fmaxf(Lr[0], Lr[1]), fmaxf(Lr[2], Lr[3]));
    float CA = EtP[0] * AhQ[0] + EtP[1] * AhQ[1] + EtP[2] * AhQ[2] + EtP[3] * AhQ[3];

    const float CLP = 86.56170245333781f;   // 60 * log2(e)
    int ldt = tid >> 1, ldh = tid & 1;      // loader lanes

    for (int t0 = 0; t0 < Ndim; t0 += 128) {
        // load x tile [128 t][8 c] -> xs2 [c][t] transposed
        {
            int n_ld = dir ? (Ndim - 1 - (t0 + ldt)) : (t0 + ldt);
            float4 v = *(const float4*)&x[((size_t)b * Ndim + n_ld) * Cdim + c0 + ldh * 4];
            xs2[(ldh * 4 + 0) * XS_STRIDE + ldt] = v.x;
            xs2[(ldh * 4 + 1) * XS_STRIDE + ldt] = v.y;
            xs2[(ldh * 4 + 2) * XS_STRIDE + ldt] = v.z;
            xs2[(ldh * 4 + 3) * XS_STRIDE + ldt] = v.w;
        }
        __syncthreads();

        float4 xq = *(const float4*)&xs2[w * XS_STRIDE + lane * 4];
        float xv[4] = {xq.x, xq.y, xq.z, xq.w};
        float yv[4];
        float s0f = (float)(t0 + lane * 4);
        float tf0 = (float)t0;

        if (lrmax * tf0 <= -CLP) {
            // ALL 4 h fully clamped: one scan of raw x, y = OFF + CA*X
            float z[4] = {xv[0], xv[1], xv[2], xv[3]};
            z[1] += z[0]; z[2] += z[1]; z[3] += z[2];
            float tot = z[3];
            float ss = tot;
#pragma unroll
            for (int o = 1; o < 32; o <<= 1) {
                float v = __shfl_up_sync(0xffffffffu, ss, o);
                if (lane >= o) ss += v;
            }
            float blkTot = __shfl_sync(0xffffffffu, ss, 31);
            float pre = ss - tot;
            float OFF = EtP[0] * carry[0] + EtP[1] * carry[1]
                      + EtP[2] * carry[2] + EtP[3] * carry[3];
#pragma unroll
            for (int j = 0; j < 4; j++)
                yv[j] = fmaf(CA, pre + z[j], OFF);
#pragma unroll
            for (int hh = 0; hh < 4; hh++)
                carry[hh] = fmaf(AhQ[hh], blkTot, carry[hh]);
        } else {
            // per-h path (v12): individual clamped/unclamped/crossing branches
            yv[0] = yv[1] = yv[2] = yv[3] = 0.0f;
#pragma unroll
            for (int hh = 0; hh < 4; hh++) {
                float lr = Lr[hh];
                float z[4], mu[4];
                if (lr * tf0 <= -CLP) {
                    float aq = AhQ[hh], ep = EtP[hh];
#pragma unroll
                    for (int j = 0; j < 4; j++) { z[j] = aq * xv[j]; mu[j] = ep; }
                } else if (lr * (tf0 + 127.0f) >= -CLP) {
                    float e0  = lr * s0f;
                    float p0  = ex2f(e0), q0 = ex2f(-e0);
                    float rp1 = ex2f(lr), rq1 = ex2f(-lr);
                    float rp2 = rp1 * rp1, rq2 = rq1 * rq1;
                    float rp3 = rp2 * rp1, rq3 = rq2 * rq1;
                    float aq0 = Ah[hh] * q0, ep0 = Et[hh] * p0;
                    z[0] = aq0 * xv[0];        mu[0] = ep0;
                    z[1] = aq0 * rq1 * xv[1];  mu[1] = ep0 * rp1;
                    z[2] = aq0 * rq2 * xv[2];  mu[2] = ep0 * rp2;
                    z[3] = aq0 * rq3 * xv[3];  mu[3] = ep0 * rp3;
                } else {
#pragma unroll
                    for (int j = 0; j < 4; j++) {
                        float e = fmaxf(lr * (s0f + (float)j), -CLP);
                        float p = ex2f(e);
                        z[j]  = Ah[hh] * xv[j] * ex2f(-e);
                        mu[j] = Et[hh] * p;
                    }
                }
                z[1] += z[0]; z[2] += z[1]; z[3] += z[2];
                float tot = z[3];
                float ss = tot;
#pragma unroll
                for (int o = 1; o < 32; o <<= 1) {
                    float v = __shfl_up_sync(0xffffffffu, ss, o);
                    if (lane >= o) ss += v;
                }
                float blkTot = __shfl_sync(0xffffffffu, ss, 31);
                float pre = ss - tot + carry[hh];
#pragma unroll
                for (int j = 0; j < 4; j++)
                    yv[j] = fmaf(mu[j], pre + z[j], yv[j]);
                carry[hh] += blkTot;
            }
        }

        *(float4*)&ys2[w * YS_STRIDE + lane * 4] = make_float4(yv[0], yv[1], yv[2], yv[3]);
        __syncthreads();

        // writers: 128 threads, each packs 8 channels for one timestep (fp16)
        if (tid < 128) {
            int n_st = dir ? (Ndim - 1 - (t0 + tid)) : (t0 + tid);
            size_t m = (size_t)b * Ndim + n_st;
            uint4 u;
            unsigned* up = (unsigned*)&u;
#pragma unroll
            for (int j = 0; j < 4; j++) {
                __half2 pk = __floats2half2_rn(ys2[(2 * j) * YS_STRIDE + tid],
                                               ys2[(2 * j + 1) * YS_STRIDE + tid]);
                up[j] = *(unsigned*)&pk;
            }
            *(uint4*)(g_a + m * Kdim + dir * Cdim + c0) = u;
        }
        __syncthreads();
    }
}

// ---------------------------------------------------------------------------
// fp16 HMMA GEMM: out[m][n] = bias[n] + sum_k z[m][k]W[n][k]
// CTA tile 128x128, K-chunk 64, 3-stage cp.async, 256 threads, 2 CTAs/SM.
// (byte-identical to v12)
// ---------------------------------------------------------------------------
#define ROWB2 144                            /* 128 data + 16 pad */
#define A_OFF 0
#define B_OFF (128*ROWB2)                    /* 18432 */
#define STG2 (2*128*ROWB2)                   /* 36864 */
#define BIAS2 (3*STG2)                       /* 110592 */
#define GSM (BIAS2 + 512)

__global__ void __launch_bounds__(256, 2) gemm_hmma(const float* __restrict__ bias,
                                                    float* __restrict__ out)
{
    extern __shared__ char smem[];
    const uint32_t sb = smem_u32(smem);
    int tid  = threadIdx.x;
    int wid  = tid >> 5, lane = tid & 31;
    int n0   = blockIdx.x * 128;
    int m0   = blockIdx.y * 128;
    int wm   = (wid & 1) * 64;
    int wn   = (wid >> 1) * 32;

    if (tid < 128) ((float*)(smem + BIAS2))[tid] = bias[n0 + tid];

    auto load_chunk = [&](int kt, int buf) {
        uint32_t st = sb + (uint32_t)buf * STG2;
        int koff = kt * 64;
#pragma unroll
        for (int i = 0; i < 4; i++) {
            int q = tid + i * 256;           // 0..1023
            int r = q >> 3, c = q & 7;
            cp16(st + A_OFF + r * ROWB2 + c * 16,
                 g_a + (size_t)(m0 + r) * Kdim + koff + c * 8);
            cp16(st + B_OFF + r * ROWB2 + c * 16,
                 g_b + (size_t)(n0 + r) * Kdim + koff + c * 8);
        }
        asm volatile("cp.async.commit_group;" ::: "memory");
    };

    const uint32_t a_off =
        (uint32_t)((wm + (lane & 7) + ((lane >> 3) & 1) * 8) * ROWB2 + ((lane >> 4) & 1) * 16);
    const uint32_t b_off =
        (uint32_t)((wn + (lane & 7) + ((lane >> 4) & 1) * 8) * ROWB2 + ((lane >> 3) & 1) * 16);

    float acc[4][4][4];
#pragma unroll
    for (int mi = 0; mi < 4; mi++)
#pragma unroll
        for (int ni = 0; ni < 4; ni++)
#pragma unroll
            for (int j = 0; j < 4; j++) acc[mi][ni][j] = 0.0f;

    load_chunk(0, 0);
    load_chunk(1, 1);

    for (int kt = 0; kt < 16; kt++) {
        if (kt + 2 < 16) load_chunk(kt + 2, (kt + 2) % 3);
        if (kt < 14)       asm volatile("cp.async.wait_group 2;" ::: "memory");
        else if (kt == 14) asm volatile("cp.async.wait_group 1;" ::: "memory");
        else               asm volatile("cp.async.wait_group 0;" ::: "memory");
        __syncthreads();

        uint32_t st = sb + (uint32_t)(kt % 3) * STG2;
#pragma unroll
        for (int s = 0; s < 4; s++) {
            uint32_t af[4][4], bf2[4][2];
#pragma unroll
            for (int mi = 0; mi < 4; mi++)
                ldsm4(af[mi], st + A_OFF + a_off + mi * 16 * ROWB2 + s * 32);
#pragma unroll
            for (int j = 0; j < 2; j++) {
                uint32_t t4[4];
                ldsm4(t4, st + B_OFF + b_off + j * 16 * ROWB2 + s * 32);
                bf2[2 * j][0] = t4[0]; bf2[2 * j][1] = t4[1];
                bf2[2 * j + 1][0] = t4[2]; bf2[2 * j + 1][1] = t4[3];
            }
#pragma unroll
            for (int mi = 0; mi < 4; mi++)
#pragma unroll
                for (int ni = 0; ni < 4; ni++)
                    mma16816(acc[mi][ni], af[mi], bf2[ni]);
        }
        __syncthreads();
    }

    asm volatile("cp.async.wait_all;" ::: "memory");
    __syncthreads();

    // epilogue: regs -> padded smem -> +bias -> coalesced float4 STG
    float* stg = (float*)smem;               // [128][132]
#pragma unroll
    for (int mi = 0; mi < 4; mi++)
#pragma unroll
        for (int ni = 0; ni < 4; ni++) {
            int r0 = wm + mi * 16 + (lane >> 2);
            int cc = wn + ni * 8 + (lane & 3) * 2;
            *(float2*)&stg[r0 * 132 + cc]       = make_float2(acc[mi][ni][0], acc[mi][ni][1]);
            *(float2*)&stg[(r0 + 8) * 132 + cc] = make_float2(acc[mi][ni][2], acc[mi][ni][3]);
        }
    __syncthreads();
    const float* bsm = (const float*)(smem + BIAS2);
#pragma unroll
    for (int i = 0; i < 16; i++) {
        int f = tid + i * 256;
        int r = f >> 5, c4 = (f & 31) * 4;
        float4 v = *(const float4*)&stg[r * 132 + c4];
        v.x += bsm[c4]; v.y += bsm[c4 + 1]; v.z += bsm[c4 + 2]; v.w += bsm[c4 + 3];
        *(float4*)&out[(size_t)(m0 + r) * Cdim + n0 + c4] = v;
    }
}

// ---------------------------------------------------------------------------
extern "C" void kernel_launch(void* const* d_in, const int* in_sizes, int n_in,
                              void* d_out, int out_size)
{
    const float* x  = (const float*)d_in[0];
    const float* al = (const float*)d_in[1];
    const float* dl = (const float*)d_in[2];
    const float* bl = (const float*)d_in[3];
    const float* et = (const float*)d_in[4];
    const float* pw = (const float*)d_in[5];
    const float* pb = (const float*)d_in[6];
    float* out = (float*)d_out;

    cudaFuncSetAttribute(gemm_hmma, cudaFuncAttributeMaxDynamicSharedMemorySize, GSM);

    wconv_kernel<<<2048, 256>>>(pw);
    scan_kernel<<<dim3(2 * Bdim * (Cdim / 8)), 256>>>(x, al, dl, bl, et);
    gemm_hmma<<<dim3(Cdim / 128, Mdim / 128), 256, GSM>>>(pb, out);
}